// round 7
// baseline (speedup 1.0000x reference)
#include <cuda_runtime.h>
#include <cuda_bf16.h>
#include <cstdint>

// Problem constants: T=32768, E=256, K=8, D=8, r=2
#define E_EXPERTS 256
#define D_DEVS    8
#define K_TOPK    8
#define E_PER_DEV (E_EXPERTS / D_DEVS)   // 32
#define TOK_PER_BLK 32                   // 8 warps x 4 tokens

__device__ int g_invperm[E_EXPERTS];

// One-time expert->slot table (ballot rank). 1 block, ~0.3us.
__global__ void setup_invperm_kernel(const int* __restrict__ mapping /* [E, D] */) {
    __shared__ int wcnt[8][8];
    const int e    = threadIdx.x;        // 256 threads
    const int lane = e & 31;
    const int w    = e >> 5;

    int best = mapping[e * D_DEVS];
    int d = 0;
#pragma unroll
    for (int i = 1; i < D_DEVS; i++) {
        int v = mapping[e * D_DEVS + i];
        if (v > best) { best = v; d = i; }   // first max wins (jnp.argmax)
    }

    const unsigned lt = (1u << lane) - 1u;
    int within = 0, mycnt = 0;
#pragma unroll
    for (int d2 = 0; d2 < D_DEVS; d2++) {
        unsigned b = __ballot_sync(0xffffffffu, d == d2);
        if (d2 == d)    within = __popc(b & lt);
        if (lane == d2) mycnt  = __popc(b);
    }
    if (lane < D_DEVS) wcnt[w][lane] = mycnt;
    __syncthreads();

    int off = 0;
#pragma unroll
    for (int w2 = 0; w2 < 8; w2++)
#pragma unroll
        for (int d2 = 0; d2 < D_DEVS; d2++) {
            int c = wcnt[w2][d2];
            off += ((d2 < d) || (d2 == d && w2 < w)) ? c : 0;
        }
    g_invperm[e] = off + within;
}

// Hot kernel: TMA bulk zero-fill (no LSU issue cost) + minimal sparse
// gather/scatter. One warp = 4 tokens; one block = 32 tokens.
__global__ __launch_bounds__(256) void moe_remap_tma(
    const float* __restrict__ topk,     // [T, E]
    const int*   __restrict__ meta,     // [T, K]
    float*       __restrict__ out,      // [D, T, 32]
    float*       __restrict__ mask,     // [T/2, D]
    int T)
{
    __shared__ __align__(128) float zbuf[TOK_PER_BLK * E_PER_DEV];  // 4KB zeros

    const int tid  = threadIdx.x;
    const int lane = tid & 31;
    const int warp = tid >> 5;
    const int quad = blockIdx.x * 8 + warp;          // 4-token group
    const int t0   = quad << 2;
    const int blkT = blockIdx.x * TOK_PER_BLK;

    // issue meta load first (independent of everything below)
    const int e = meta[t0 * K_TOPK + lane];          // 32 contiguous ints

    // zero the 4KB smem source for the bulk stores: one STS.128 per thread
    reinterpret_cast<float4*>(zbuf)[tid] = make_float4(0.f, 0.f, 0.f, 0.f);
    asm volatile("fence.proxy.async.shared::cta;" ::: "memory");
    __syncthreads();

    // thread 0: 8 bulk stores (one 4KB plane-slice each) — async proxy
    uint32_t zbuf_addr;
    asm("{ .reg .u64 t; cvta.to.shared.u64 t, %1; cvt.u32.u64 %0, t; }"
        : "=r"(zbuf_addr) : "l"(zbuf));
    if (tid == 0) {
#pragma unroll
        for (int dd = 0; dd < D_DEVS; dd++) {
            float* gdst = out + dd * (T * E_PER_DEV) + blkT * E_PER_DEV;
            asm volatile(
                "cp.async.bulk.global.shared::cta.bulk_group [%0], [%1], %2;"
                :: "l"(gdst), "r"(zbuf_addr), "r"(TOK_PER_BLK * E_PER_DEV * 4)
                : "memory");
        }
        asm volatile("cp.async.bulk.commit_group;" ::: "memory");
    }

    // gather chain overlaps the bulk-fill drain
    const int tl = lane >> 3;                               // local token 0..3
    const float v = topk[(t0 + tl) * E_EXPERTS + e];        // sparse gather
    const int p  = g_invperm[e];                            // L2/L1-hot table
    const int d  = p >> 5, j = p & 31;

    // pair masks: OR within 16-lane halves (tokens {0,1} | {2,3})
    const unsigned pm = (lane < 16) ? 0x0000ffffu : 0xffff0000u;
    const unsigned r  = __reduce_or_sync(pm, 1u << d);
    const unsigned hr = __shfl_sync(0xffffffffu, r, 16);    // high-half result

    // order scatter after this block's zero-fill
    if (tid == 0)
        asm volatile("cp.async.bulk.wait_group 0;" ::: "memory");
    __syncthreads();

    // sparse scatter (duplicate (token,expert) selections write same value)
    out[d * (T * E_PER_DEV) + (t0 + tl) * E_PER_DEV + j] = v;

    // mask rows: quad covers pairs 2q, 2q+1 -> 16 floats, lanes 0..15
    if (lane < 16) {
        const unsigned bits = (lane < 8) ? r : hr;
        mask[quad * 16 + lane] = ((bits >> (lane & 7)) & 1u) ? 1.0f : 0.0f;
    }
}

extern "C" void kernel_launch(void* const* d_in, const int* in_sizes, int n_in,
                              void* d_out, int out_size) {
    const float* topk    = (const float*)d_in[0];   // [1,1,T,E]
    const int*   mapping = (const int*)  d_in[1];   // [1,1,E,D]
    const int*   meta    = (const int*)  d_in[2];   // [1,1,T,K]

    const int T = in_sizes[0] / E_EXPERTS;          // 32768

    float* out  = (float*)d_out;                            // [D, T, 32]
    float* mask = out + (size_t)D_DEVS * T * E_PER_DEV;     // [T/2, D]

    setup_invperm_kernel<<<1, E_EXPERTS>>>(mapping);

    const int blocks = T / TOK_PER_BLK;             // 1024
    moe_remap_tma<<<blocks, 256>>>(topk, meta, out, mask, T);
}

// round 8
// speedup vs baseline: 1.3701x; 1.3701x over previous
#include <cuda_runtime.h>
#include <cuda_bf16.h>
#include <cstdint>

// Problem constants: T=32768, E=256, K=8, D=8, r=2
#define E_EXPERTS 256
#define D_DEVS    8
#define K_TOPK    8
#define E_PER_DEV (E_EXPERTS / D_DEVS)   // 32
#define TOK_PER_BLK 32                   // 8 warps x 4 tokens

// Single fused kernel. Block = 32 tokens. All global writes of the dense
// output go through TMA bulk stores from a fully-constructed smem slice.
__global__ __launch_bounds__(256) void moe_remap_build(
    const float* __restrict__ topk,     // [T, E]
    const int*   __restrict__ mapping,  // [E, D] one-hot
    const int*   __restrict__ meta,     // [T, K]
    float*       __restrict__ out,      // [D, T, 32]
    float*       __restrict__ mask,     // [T/2, D]
    int T)
{
    __shared__ __align__(128) float sdata[D_DEVS * TOK_PER_BLK * E_PER_DEV]; // 32KB
    __shared__ int wcnt_s[64];          // [warp][device]
    __shared__ int C_s[64];             // exclusive prefix in (device-major) order
    __shared__ int invperm_s[E_EXPERTS];

    const int tid  = threadIdx.x;
    const int lane = tid & 31;
    const int warp = tid >> 5;
    const int quad = blockIdx.x * 8 + warp;      // 4-token group
    const int t0   = quad << 2;
    const int blkT = blockIdx.x * TOK_PER_BLK;

    // ---- independent loads first ----
    const int e = meta[t0 * K_TOPK + lane];      // lane's selection (coalesced)

    // expert tid's device (argmax, first max wins)
    const int4 a4 = reinterpret_cast<const int4*>(mapping)[tid * 2];
    const int4 b4 = reinterpret_cast<const int4*>(mapping)[tid * 2 + 1];
    int v8[8] = {a4.x, a4.y, a4.z, a4.w, b4.x, b4.y, b4.z, b4.w};
    int best = v8[0], d = 0;
#pragma unroll
    for (int i = 1; i < D_DEVS; i++)
        if (v8[i] > best) { best = v8[i]; d = i; }

    // ballots: rank within warp, per-device counts
    const unsigned lt = (1u << lane) - 1u;
    int within = 0, mycnt = 0;
#pragma unroll
    for (int d2 = 0; d2 < D_DEVS; d2++) {
        unsigned b = __ballot_sync(0xffffffffu, d == d2);
        if (d2 == d)    within = __popc(b & lt);
        if (lane == d2) mycnt  = __popc(b);
    }
    if (lane < D_DEVS) wcnt_s[warp * 8 + lane] = mycnt;

    __syncthreads();   // wcnt visible

    // ---- warp 0: exclusive scan of the 64 counts in (d*8 + w) order ----
    if (warp == 0) {
        // element f: value wcnt_s[w*8+d] with d=f>>3, w=f&7
        int x0 = wcnt_s[(lane & 7) * 8 + (lane >> 3)];            // f = lane
        int x1 = wcnt_s[((lane + 32) & 7) * 8 + ((lane + 32) >> 3)]; // f = lane+32
        int i0 = x0, i1 = x1;
#pragma unroll
        for (int o = 1; o < 32; o <<= 1) {
            int y0 = __shfl_up_sync(0xffffffffu, i0, o);
            int y1 = __shfl_up_sync(0xffffffffu, i1, o);
            if (lane >= o) { i0 += y0; i1 += y1; }
        }
        const int tot0 = __shfl_sync(0xffffffffu, i0, 31);
        C_s[lane]      = i0 - x0;               // exclusive
        C_s[lane + 32] = i1 - x1 + tot0;
    }
    // ---- all warps: zero their 4KB share of sdata (8 x STS.128) ----
    {
        float4* s4 = reinterpret_cast<float4*>(sdata);
        const float4 z = make_float4(0.f, 0.f, 0.f, 0.f);
#pragma unroll
        for (int i = 0; i < 8; i++) s4[tid + 256 * i] = z;
    }
    // gather value (needs e only; overlaps everything)
    const int tl = lane >> 3;                                // local token 0..3
    const float gv = topk[(t0 + tl) * E_EXPERTS + e];

    __syncthreads();   // C_s + zeros visible

    invperm_s[tid] = C_s[d * 8 + warp] + within;             // expert tid -> slot

    __syncthreads();   // invperm table ready

    // ---- scatter into smem slice ----
    const int p  = invperm_s[e];
    const int ds = p >> 5, js = p & 31;
    const int tokb = warp * 4 + tl;                          // token in block
    sdata[ds * (TOK_PER_BLK * E_PER_DEV) + tokb * E_PER_DEV + js] = gv;

    // ---- pair masks (tokens {0,1} | {2,3} per warp) ----
    const unsigned pm = (lane < 16) ? 0x0000ffffu : 0xffff0000u;
    const unsigned r  = __reduce_or_sync(pm, 1u << ds);
    const unsigned hr = __shfl_sync(0xffffffffu, r, 16);
    if (lane < 16) {
        const unsigned bits = (lane < 8) ? r : hr;
        mask[quad * 16 + lane] = ((bits >> (lane & 7)) & 1u) ? 1.0f : 0.0f;
    }

    // ---- make smem visible to async proxy, then bulk-store 8 planes ----
    asm volatile("fence.proxy.async.shared::cta;" ::: "memory");
    __syncthreads();

    if (tid == 0) {
        uint32_t saddr;
        asm("{ .reg .u64 t; cvta.to.shared.u64 t, %1; cvt.u32.u64 %0, t; }"
            : "=r"(saddr) : "l"(sdata));
#pragma unroll
        for (int dd = 0; dd < D_DEVS; dd++) {
            float* gdst = out + dd * (T * E_PER_DEV) + blkT * E_PER_DEV;
            asm volatile(
                "cp.async.bulk.global.shared::cta.bulk_group [%0], [%1], %2;"
                :: "l"(gdst),
                   "r"(saddr + dd * (TOK_PER_BLK * E_PER_DEV * 4)),
                   "r"(TOK_PER_BLK * E_PER_DEV * 4)
                : "memory");
        }
        asm volatile("cp.async.bulk.commit_group;" ::: "memory");
        // block may exit once TMA has *read* the smem; writes drain async
        asm volatile("cp.async.bulk.wait_group.read 0;" ::: "memory");
    }
}

extern "C" void kernel_launch(void* const* d_in, const int* in_sizes, int n_in,
                              void* d_out, int out_size) {
    const float* topk    = (const float*)d_in[0];   // [1,1,T,E]
    const int*   mapping = (const int*)  d_in[1];   // [1,1,E,D]
    const int*   meta    = (const int*)  d_in[2];   // [1,1,T,K]

    const int T = in_sizes[0] / E_EXPERTS;          // 32768

    float* out  = (float*)d_out;                            // [D, T, 32]
    float* mask = out + (size_t)D_DEVS * T * E_PER_DEV;     // [T/2, D]

    const int blocks = T / TOK_PER_BLK;             // 1024
    moe_remap_build<<<blocks, 256>>>(topk, mapping, meta, out, mask, T);
}